// round 14
// baseline (speedup 1.0000x reference)
#include <cuda_runtime.h>
#include <cstddef>
#include <cstdint>

// Problem constants (fixed by the reference)
#define BB 8
#define DD 32
#define NPIX 262144          // 512*512
#define KK 16

// Pass-1 tiling: 64 chunks x 2 d-groups x 8 images = 1024 blocks
#define P1_CHUNK  4096
#define P1_NCHUNK (NPIX / P1_CHUNK)    // 64
#define TILE      256                  // pixels per staged tile
#define NTILES    (P1_CHUNK / TILE)    // 16

// Pass-2 tiling
#define P2_TPB    256
#define P2_BLOCKS (NPIX / 4 / P2_TPB)  // 256 blocks per image

// Dynamic smem layout for pass1 (floats unless noted)
#define ACC_F   (16 * KK * 32)                 // 8192 f = 32 KB
#define CNT_F   (KK * 32)                      // 512 f  = 2 KB
#define LAB_W   (P1_CHUNK / 4)                 // 1024 u32 = 4 KB
#define BUF_F   (16 * TILE)                    // 4096 f = 16 KB per buffer
#define SMEM_P1 ((ACC_F + CNT_F + 2 * BUF_F) * 4 + LAB_W * 4)  // 71680 B

// Scratch (no cudaMalloc allowed). Partials fully overwritten each launch.
__device__ float g_part[BB * P1_NCHUNK * KK * DD];
__device__ float g_cntp[BB * P1_NCHUNK * KK];
__device__ float g_counts[BB * KK];
__device__ float g_means[BB * KK * DD];

__device__ __forceinline__ uint32_t smem_u32(const void* p) {
    return (uint32_t)__cvta_generic_to_shared(p);
}
__device__ __forceinline__ void cp16(uint32_t dst, const void* src) {
    asm volatile("cp.async.cg.shared.global [%0], [%1], 16;" :: "r"(dst), "l"(src));
}
__device__ __forceinline__ void cp_commit() {
    asm volatile("cp.async.commit_group;" ::: "memory");
}
__device__ __forceinline__ void cp_wait1() {
    asm volatile("cp.async.wait_group 1;" ::: "memory");
}

// ---------------------------------------------------------------------------
// Pass 1: per-image, per-chunk partial segment sums.
// cp.async staged: embeddings stream global->smem via LDGSTS (bypasses the
// per-SM in-order L1tex wavefront return FIFO), so the RMW phase's LDS ops
// keep their native ~29cyc latency instead of queueing behind DRAM misses.
// Double-buffered 256px x 16-plane tiles; warp w RMWs plane d = dg*16 + w
// from smem. Per-lane privatized bins (stride 32), conflict-free.
// ---------------------------------------------------------------------------
__global__ __launch_bounds__(512) void k_pass1(const float* __restrict__ emb,
                                               const int* __restrict__ gt,
                                               float* out) {
    extern __shared__ float sm[];
    float*    acc  = sm;                        // [16 warps][16 k][32 lanes]
    float*    cnt  = sm + ACC_F;                // [16 k][32 lanes]
    unsigned* labw = (unsigned*)(sm + ACC_F + CNT_F);   // packed u8x4
    float*    buf  = sm + ACC_F + CNT_F + LAB_W;        // 2 x [16 planes][256 px]

    const int b  = blockIdx.z;
    const int dg = blockIdx.y;
    const int c  = blockIdx.x;
    const int p0 = c * P1_CHUNK;
    const int tid = threadIdx.x;
    const int w   = tid >> 5;
    const int lane = tid & 31;
    const int d = dg * 16 + w;

    if (b == 0 && dg == 0 && c == 0 && tid == 0) out[0] = 0.0f;

    // Per-thread staging descriptors: 1024 16B-chunks per tile, 512 threads,
    // 2 cp.async each. idx -> (plane = idx>>6, f4 = idx&63).
    const int idx0 = tid, idx1 = tid + 512;
    const float* src0 = emb + ((size_t)(b * DD + dg * 16 + (idx0 >> 6))) * NPIX
                        + p0 + (idx0 & 63) * 4;
    const float* src1 = emb + ((size_t)(b * DD + dg * 16 + (idx1 >> 6))) * NPIX
                        + p0 + (idx1 & 63) * 4;
    const uint32_t bufa = smem_u32(buf);
    const uint32_t d0a = bufa + (uint32_t)(((idx0 >> 6) * TILE + (idx0 & 63) * 4) * 4);
    const uint32_t d1a = bufa + (uint32_t)(((idx1 >> 6) * TILE + (idx1 & 63) * 4) * 4);

    // Prologue: stage tile 0 into buffer 0.
    cp16(d0a, src0);
    cp16(d1a, src1);
    cp_commit();

    // Zero bins; stage+pack labels (plain loads, one-time).
    for (int j = tid; j < ACC_F; j += 512) acc[j] = 0.0f;
    if (tid < CNT_F) cnt[tid] = 0.0f;
    const int4* g4 = (const int4*)(gt + (size_t)b * NPIX + p0);
    #pragma unroll
    for (int j = 0; j < LAB_W / 512; j++) {
        int4 t = __ldg(&g4[j * 512 + tid]);
        labw[j * 512 + tid] = (unsigned)t.x | ((unsigned)t.y << 8) |
                              ((unsigned)t.z << 16) | ((unsigned)t.w << 24);
    }

    const bool docnt = (dg == 0) && (w == 0);
    float* aw = acc + (w * KK) * 32 + lane;
    float* cw = cnt + lane;

    #define RMW(V, KW) do {                                             \
        unsigned kw_ = (KW);                                            \
        aw[(int)(kw_ & 15u) * 32]         += (V).x;                     \
        aw[(int)((kw_ >> 8) & 15u) * 32]  += (V).y;                     \
        aw[(int)((kw_ >> 16) & 15u) * 32] += (V).z;                     \
        aw[(int)(kw_ >> 24) * 32]         += (V).w;                     \
    } while (0)
    #define CNT(KW) do {                                                \
        unsigned kw_ = (KW);                                            \
        cw[(int)(kw_ & 15u) * 32]         += 1.0f;                      \
        cw[(int)((kw_ >> 8) & 15u) * 32]  += 1.0f;                      \
        cw[(int)((kw_ >> 16) & 15u) * 32] += 1.0f;                      \
        cw[(int)(kw_ >> 24) * 32]         += 1.0f;                      \
    } while (0)

    #pragma unroll 1
    for (int t = 0; t < NTILES; t++) {
        // Stage tile t+1 into the other buffer (overlaps with RMW of t).
        if (t + 1 < NTILES) {
            const int toff = (t + 1) * TILE;
            const uint32_t sel = (uint32_t)((t + 1) & 1) << 14;  // *16KB
            cp16(d0a + sel, src0 + toff);
            cp16(d1a + sel, src1 + toff);
        }
        cp_commit();
        cp_wait1();                 // tile t's group complete
        __syncthreads();            // cross-thread visibility of buf + labw/zero

        const float* bw = buf + ((t & 1) * (16 * TILE)) + w * TILE;
        float4 v0 = *(const float4*)(bw + lane * 4);
        float4 v1 = *(const float4*)(bw + 128 + lane * 4);
        unsigned k0 = labw[t * 64 + lane];
        unsigned k1 = labw[t * 64 + 32 + lane];

        RMW(v0, k0);
        RMW(v1, k1);
        if (docnt) { CNT(k0); CNT(k1); }

        __syncthreads();            // all reads of buf[t&1] done before restage
    }
    #undef RMW
    #undef CNT

    // Epilogue: rows acc[w][k][0..31] are contiguous 128B. 2 lanes per k-row,
    // each reads 4 float4, sum, 1 shuffle, STG (no atomics).
    {
        const int k = lane >> 1;
        const int h = lane & 1;
        const float4* row = (const float4*)(acc + ((w * KK + k) << 5) + (h << 4));
        float4 r0 = row[0], r1 = row[1], r2 = row[2], r3 = row[3];
        float s = ((r0.x + r0.y) + (r0.z + r0.w)) + ((r1.x + r1.y) + (r1.z + r1.w))
                + ((r2.x + r2.y) + (r2.z + r2.w)) + ((r3.x + r3.y) + (r3.z + r3.w));
        s += __shfl_down_sync(0xffffffffu, s, 1);
        if (h == 0)
            g_part[(((b * P1_NCHUNK + c) * KK + k) * DD) + d] = s;
    }
    if (docnt) {
        const int k = lane >> 1;
        const int h = lane & 1;
        const float4* row = (const float4*)(cnt + (k << 5) + (h << 4));
        float4 r0 = row[0], r1 = row[1], r2 = row[2], r3 = row[3];
        float s = ((r0.x + r0.y) + (r0.z + r0.w)) + ((r1.x + r1.y) + (r1.z + r1.w))
                + ((r2.x + r2.y) + (r2.z + r2.w)) + ((r3.x + r3.y) + (r3.z + r3.w));
        s += __shfl_down_sync(0xffffffffu, s, 1);
        if (h == 0)
            g_cntp[(b * P1_NCHUNK + c) * KK + k] = s;
    }
}

// ---------------------------------------------------------------------------
// Finalize: reduce partials -> counts & means; pairwise push loss; reg loss.
// ---------------------------------------------------------------------------
__global__ __launch_bounds__(256) void k_finalize(float* out) {
    __shared__ float m[KK * 33];
    __shared__ float cs[KK];
    __shared__ float red[256];

    const int b = blockIdx.x;
    const int tid = threadIdx.x;

    if (tid < KK) {
        float s = 0.0f;
        #pragma unroll 4
        for (int c = 0; c < P1_NCHUNK; c++)
            s += g_cntp[(b * P1_NCHUNK + c) * KK + tid];
        float cv = fmaxf(s, 1.0f);
        cs[tid] = cv;
        g_counts[b * KK + tid] = cv;
    }
    __syncthreads();

    for (int j = tid; j < KK * DD; j += 256) {
        int k = j >> 5, d = j & 31;
        float s = 0.0f;
        #pragma unroll 4
        for (int c = 0; c < P1_NCHUNK; c++)
            s += g_part[(((b * P1_NCHUNK + c) * KK + k) * DD) + d];
        float mean = s / cs[k];
        g_means[(b * KK + k) * DD + d] = mean;
        m[k * 33 + d] = mean;
    }
    __syncthreads();

    const int i = tid >> 4;
    const int j = tid & 15;
    float contrib = 0.0f;
    if (j > i) {
        float d2 = 0.0f;
        #pragma unroll
        for (int d = 0; d < DD; d++) {
            float df = m[i * 33 + d] - m[j * 33 + d];
            d2 = fmaf(df, df, d2);
        }
        float pd = sqrtf(d2);
        float h = fmaxf(3.0f - pd, 0.0f);
        contrib = h * h;
    }

    float reg = 0.0f;
    if (tid < KK) {
        float n2 = 0.0f;
        #pragma unroll
        for (int d = 0; d < DD; d++) {
            float v = m[tid * 33 + d];
            n2 = fmaf(v, v, n2);
        }
        reg = sqrtf(n2);
    }

    red[tid] = contrib * (1.0f / (KK * (KK - 1))) + 0.001f * reg * (1.0f / KK);
    __syncthreads();
    for (int off = 128; off; off >>= 1) {
        if (tid < off) red[tid] += red[tid + off];
        __syncthreads();
    }
    if (tid == 0) atomicAdd(out, red[0] * (1.0f / BB));
}

// ---------------------------------------------------------------------------
// Pass 2: per-pixel hinge variance loss. Reversed traversal (harvest L2
// leftovers from pass1 first); __ldcs = last consumer, evict-first.
// ---------------------------------------------------------------------------
__global__ __launch_bounds__(P2_TPB) void k_pass2(const float* __restrict__ emb,
                                                  const int* __restrict__ gt,
                                                  float* out) {
    __shared__ float m[KK * 33];
    __shared__ float wk[KK];
    __shared__ float red[P2_TPB / 32];

    const int b  = (BB - 1) - blockIdx.y;
    const int xr = (P2_BLOCKS - 1) - blockIdx.x;
    const int tid = threadIdx.x;
    const int lane = tid & 31;
    const int w = tid >> 5;
    const int p4 = xr * P2_TPB + tid;

    for (int j = tid; j < KK * DD; j += P2_TPB)
        m[(j / DD) * 33 + (j % DD)] = g_means[b * KK * DD + j];
    if (tid < KK)
        wk[tid] = 1.0f / ((float)KK * fmaxf(g_counts[b * KK + tid], 1.0f));
    __syncthreads();

    const float4* e4 = (const float4*)(emb + (size_t)b * DD * NPIX);
    const int4 kk = ((const int4*)(gt + (size_t)b * NPIX))[p4];

    const float* m0 = m + kk.x * 33;
    const float* m1 = m + kk.y * 33;
    const float* m2 = m + kk.z * 33;
    const float* m3 = m + kk.w * 33;

    float a0 = 0.0f, a1 = 0.0f, a2 = 0.0f, a3 = 0.0f;
    #pragma unroll
    for (int g = 0; g < 4; g++) {
        float4 v[8];
        #pragma unroll
        for (int j = 0; j < 8; j++)
            v[j] = __ldcs(&e4[(size_t)(g * 8 + j) * (NPIX / 4) + p4]);
        #pragma unroll
        for (int j = 0; j < 8; j++) {
            const int d = g * 8 + j;
            float t;
            t = v[j].x - m0[d]; a0 = fmaf(t, t, a0);
            t = v[j].y - m1[d]; a1 = fmaf(t, t, a1);
            t = v[j].z - m2[d]; a2 = fmaf(t, t, a2);
            t = v[j].w - m3[d]; a3 = fmaf(t, t, a3);
        }
    }

    float h, lacc = 0.0f;
    h = fmaxf(sqrtf(a0) - 0.5f, 0.0f); lacc = fmaf(h * h, wk[kk.x], lacc);
    h = fmaxf(sqrtf(a1) - 0.5f, 0.0f); lacc = fmaf(h * h, wk[kk.y], lacc);
    h = fmaxf(sqrtf(a2) - 0.5f, 0.0f); lacc = fmaf(h * h, wk[kk.z], lacc);
    h = fmaxf(sqrtf(a3) - 0.5f, 0.0f); lacc = fmaf(h * h, wk[kk.w], lacc);

    #pragma unroll
    for (int off = 16; off; off >>= 1)
        lacc += __shfl_down_sync(0xffffffffu, lacc, off);
    if (lane == 0) red[w] = lacc;
    __syncthreads();
    if (tid == 0) {
        float s = 0.0f;
        #pragma unroll
        for (int i = 0; i < P2_TPB / 32; i++) s += red[i];
        atomicAdd(out, s * (1.0f / BB));
    }
}

// ---------------------------------------------------------------------------
extern "C" void kernel_launch(void* const* d_in, const int* in_sizes, int n_in,
                              void* d_out, int out_size) {
    int ei = 0, gi = 1;
    if (n_in >= 2 && in_sizes[0] == BB * NPIX) { ei = 1; gi = 0; }

    const float* emb = (const float*)d_in[ei];
    const int*   gt  = (const int*)d_in[gi];
    float* out = (float*)d_out;

    // Idempotent attribute set (host-side, not an allocation; capture-safe).
    cudaFuncSetAttribute(k_pass1, cudaFuncAttributeMaxDynamicSharedMemorySize,
                         SMEM_P1);

    k_pass1<<<dim3(P1_NCHUNK, 2, BB), 512, SMEM_P1>>>(emb, gt, out);
    k_finalize<<<BB, 256>>>(out);
    k_pass2<<<dim3(P2_BLOCKS, BB), P2_TPB>>>(emb, gt, out);
}

// round 15
// speedup vs baseline: 1.1669x; 1.1669x over previous
#include <cuda_runtime.h>
#include <cstddef>

// Problem constants (fixed by the reference)
#define BB 8
#define DD 32
#define NPIX 262144          // 512*512
#define KK 16

// Pass-1 tiling: 32 pixel-chunks x 2 d-groups x 8 images = 512 blocks
#define P1_CHUNK  8192
#define P1_NCHUNK (NPIX / P1_CHUNK)    // 32

// Pass-2 tiling: one float4 (4 pixels) per thread
#define P2_TPB    256
#define P2_BLOCKS (NPIX / 4 / P2_TPB)  // 256 blocks per image

// Scratch (no cudaMalloc allowed). Partials fully overwritten each launch.
__device__ float g_part[BB * P1_NCHUNK * KK * DD];   // per-chunk partial sums
__device__ float g_cntp[BB * P1_NCHUNK * KK];        // per-chunk partial counts
__device__ float g_counts[BB * KK];
__device__ float g_means[BB * KK * DD];

// ---------------------------------------------------------------------------
// Count kernel: label histogram per (image, chunk). Runs FIRST: reads only
// the 8 MB label array (warming L2 for pass1's label staging) and fills
// g_cntp so pass1 carries ZERO counting work -> all 16 pass1 warps identical
// (removes the dg0/warp0 straggler that gated half of pass1's blocks).
// Per-warp privatized bins, same conflict-free stride-32 pattern as pass1.
// ---------------------------------------------------------------------------
__global__ __launch_bounds__(256) void k_count(const int* __restrict__ gt,
                                               float* out) {
    __shared__ float cw8[8 * KK * 32];   // [warp][k][lane] 16 KB
    __shared__ float tot[8 * KK];

    const int b = blockIdx.y;
    const int c = blockIdx.x;
    const int tid = threadIdx.x;
    const int w = tid >> 5;
    const int lane = tid & 31;

    if (b == 0 && c == 0 && tid == 0) out[0] = 0.0f;

    float* cw = cw8 + (w * KK) * 32 + lane;
    #pragma unroll
    for (int k = 0; k < KK; k++) cw[k * 32] = 0.0f;
    __syncwarp();

    // 2048 int4 per chunk; thread handles 8.
    const int4* g4 = (const int4*)(gt + (size_t)b * NPIX + c * P1_CHUNK);
    #pragma unroll
    for (int j = 0; j < 8; j++) {
        int4 t = __ldg(&g4[j * 256 + tid]);
        cw[t.x * 32] += 1.0f;
        cw[t.y * 32] += 1.0f;
        cw[t.z * 32] += 1.0f;
        cw[t.w * 32] += 1.0f;
    }
    __syncwarp();

    // Per-warp reduce: k-row = 32 floats = 128B contiguous; 2 lanes per row.
    {
        const int k = lane >> 1;
        const int h = lane & 1;
        const float4* row = (const float4*)(cw8 + ((w * KK + k) << 5) + (h << 4));
        float4 r0 = row[0], r1 = row[1], r2 = row[2], r3 = row[3];
        float s = ((r0.x + r0.y) + (r0.z + r0.w)) + ((r1.x + r1.y) + (r1.z + r1.w))
                + ((r2.x + r2.y) + (r2.z + r2.w)) + ((r3.x + r3.y) + (r3.z + r3.w));
        s += __shfl_down_sync(0xffffffffu, s, 1);
        if (h == 0) tot[w * KK + k] = s;
    }
    __syncthreads();

    if (tid < KK) {
        float s = 0.0f;
        #pragma unroll
        for (int ww = 0; ww < 8; ww++) s += tot[ww * KK + tid];
        g_cntp[(b * P1_NCHUNK + c) * KK + tid] = s;
    }
}

// ---------------------------------------------------------------------------
// Pass 1: per-image, per-chunk partial segment sums. (R13 minus counting.)
// Block = 512 threads = 16 warps; warp w owns plane d = dg*16 + w over the
// whole 8192-px chunk. Software-pipelined (distance 1). Embeddings loaded
// with DEFAULT policy (__ldg): pass1 is the first reader, leaving the stream
// L2-resident for pass2. All warps do identical work (no count straggler).
// Per-lane privatized smem bins (stride 32): LDS/FADD/STS conflict-free.
// ---------------------------------------------------------------------------
__global__ __launch_bounds__(512) void k_pass1(const float* __restrict__ emb,
                                               const int* __restrict__ gt) {
    __shared__ float acc[16 * KK * 32];          // [w][k][lane]  32 KB
    __shared__ unsigned int labw[P1_CHUNK / 4];  // packed 4x u8    8 KB

    const int b  = blockIdx.z;
    const int dg = blockIdx.y;                   // d group: 0 or 1
    const int c  = blockIdx.x;                   // chunk
    const int p0 = c * P1_CHUNK;
    const int tid = threadIdx.x;
    const int w   = tid >> 5;
    const int lane = tid & 31;
    const int d = dg * 16 + w;

    for (int j = tid; j < 16 * KK * 32; j += 512) acc[j] = 0.0f;

    // Stage labels once (int4 -> packed u8x4): 2048 words (L2-hot via k_count)
    const int4* g4 = (const int4*)(gt + (size_t)b * NPIX + p0);
    for (int j = tid; j < P1_CHUNK / 4; j += 512) {
        int4 t = g4[j];
        labw[j] = (unsigned)t.x | ((unsigned)t.y << 8) |
                  ((unsigned)t.z << 16) | ((unsigned)t.w << 24);
    }
    __syncthreads();

    const float4* e4 = (const float4*)(emb + ((size_t)(b * DD + d)) * NPIX + p0);

    float* aw = acc + (w * KK) * 32 + lane;

    #define RMW(V, KW) do {                                             \
        unsigned kw_ = (KW);                                            \
        aw[(int)(kw_ & 15u) * 32]         += (V).x;                     \
        aw[(int)((kw_ >> 8) & 15u) * 32]  += (V).y;                     \
        aw[(int)((kw_ >> 16) & 15u) * 32] += (V).z;                     \
        aw[(int)(kw_ >> 24) * 32]         += (V).w;                     \
    } while (0)

    // 2048 float4s per plane-chunk per warp; 64 per lane, two per iteration.
    // Software pipeline, prefetch distance 1. Default-policy loads (L2-keep).
    float4 va = __ldg(&e4[lane]);
    float4 vb = __ldg(&e4[lane + 32]);
    unsigned ka = labw[lane];
    unsigned kb = labw[lane + 32];

    #pragma unroll 1
    for (int i = 0; i < 31; i++) {
        const int nidx = (i + 1) * 64 + lane;
        float4 na = __ldg(&e4[nidx]);
        float4 nb = __ldg(&e4[nidx + 32]);
        unsigned nka = labw[nidx];
        unsigned nkb = labw[nidx + 32];

        RMW(va, ka);
        RMW(vb, kb);

        va = na; vb = nb; ka = nka; kb = nkb;
    }
    RMW(va, ka);
    RMW(vb, kb);
    #undef RMW
    __syncwarp();

    // Epilogue: rows acc[w][k][0..31] are contiguous 128B. 2 lanes per k-row,
    // each reads 4 float4, sum, 1 shuffle, STG (no atomics).
    {
        const int k = lane >> 1;
        const int h = lane & 1;
        const float4* row = (const float4*)(acc + ((w * KK + k) << 5) + (h << 4));
        float4 r0 = row[0], r1 = row[1], r2 = row[2], r3 = row[3];
        float s = ((r0.x + r0.y) + (r0.z + r0.w)) + ((r1.x + r1.y) + (r1.z + r1.w))
                + ((r2.x + r2.y) + (r2.z + r2.w)) + ((r3.x + r3.y) + (r3.z + r3.w));
        s += __shfl_down_sync(0xffffffffu, s, 1);
        if (h == 0)
            g_part[(((b * P1_NCHUNK + c) * KK + k) * DD) + d] = s;
    }
}

// ---------------------------------------------------------------------------
// Finalize: reduce partials -> counts & means; pairwise push loss; reg loss.
// One block per image.
// ---------------------------------------------------------------------------
__global__ __launch_bounds__(256) void k_finalize(float* out) {
    __shared__ float m[KK * 33];    // padded means
    __shared__ float cs[KK];
    __shared__ float red[256];

    const int b = blockIdx.x;
    const int tid = threadIdx.x;

    if (tid < KK) {
        float s = 0.0f;
        #pragma unroll 4
        for (int c = 0; c < P1_NCHUNK; c++)
            s += g_cntp[(b * P1_NCHUNK + c) * KK + tid];
        float cv = fmaxf(s, 1.0f);
        cs[tid] = cv;
        g_counts[b * KK + tid] = cv;
    }
    __syncthreads();

    for (int j = tid; j < KK * DD; j += 256) {
        int k = j >> 5, d = j & 31;
        float s = 0.0f;
        #pragma unroll 4
        for (int c = 0; c < P1_NCHUNK; c++)
            s += g_part[(((b * P1_NCHUNK + c) * KK + k) * DD) + d];
        float mean = s / cs[k];
        g_means[(b * KK + k) * DD + d] = mean;
        m[k * 33 + d] = mean;
    }
    __syncthreads();

    // Pairwise hinge on cluster-mean distances: thread -> (i,j), upper tri only.
    const int i = tid >> 4;
    const int j = tid & 15;
    float contrib = 0.0f;
    if (j > i) {
        float d2 = 0.0f;
        #pragma unroll
        for (int d = 0; d < DD; d++) {
            float df = m[i * 33 + d] - m[j * 33 + d];
            d2 = fmaf(df, df, d2);
        }
        float pd = sqrtf(d2);             // i<j: diagonal eye irrelevant
        float h = fmaxf(3.0f - pd, 0.0f); // 2 * DIST_THETA = 3.0
        contrib = h * h;
    }

    float reg = 0.0f;
    if (tid < KK) {
        float n2 = 0.0f;
        #pragma unroll
        for (int d = 0; d < DD; d++) {
            float v = m[tid * 33 + d];
            n2 = fmaf(v, v, n2);
        }
        reg = sqrtf(n2);
    }

    red[tid] = contrib * (1.0f / (KK * (KK - 1))) + 0.001f * reg * (1.0f / KK);
    __syncthreads();
    for (int off = 128; off; off >>= 1) {
        if (tid < off) red[tid] += red[tid + off];
        __syncthreads();
    }
    if (tid == 0) atomicAdd(out, red[0] * (1.0f / BB));
}

// ---------------------------------------------------------------------------
// Pass 2: per-pixel hinge variance loss. Reversed traversal (harvest pass1's
// L2 leftovers first); __ldcs = last consumer, evict-first.
// ---------------------------------------------------------------------------
__global__ __launch_bounds__(P2_TPB) void k_pass2(const float* __restrict__ emb,
                                                  const int* __restrict__ gt,
                                                  float* out) {
    __shared__ float m[KK * 33];
    __shared__ float wk[KK];
    __shared__ float red[P2_TPB / 32];

    const int b  = (BB - 1) - blockIdx.y;                 // image reversal
    const int xr = (P2_BLOCKS - 1) - blockIdx.x;          // chunk reversal
    const int tid = threadIdx.x;
    const int lane = tid & 31;
    const int w = tid >> 5;
    const int p4 = xr * P2_TPB + tid;            // float4 index

    for (int j = tid; j < KK * DD; j += P2_TPB)
        m[(j / DD) * 33 + (j % DD)] = g_means[b * KK * DD + j];
    if (tid < KK)
        wk[tid] = 1.0f / ((float)KK * fmaxf(g_counts[b * KK + tid], 1.0f));
    __syncthreads();

    const float4* e4 = (const float4*)(emb + (size_t)b * DD * NPIX);
    const int4 kk = ((const int4*)(gt + (size_t)b * NPIX))[p4];

    const float* m0 = m + kk.x * 33;
    const float* m1 = m + kk.y * 33;
    const float* m2 = m + kk.z * 33;
    const float* m3 = m + kk.w * 33;

    float a0 = 0.0f, a1 = 0.0f, a2 = 0.0f, a3 = 0.0f;
    #pragma unroll
    for (int g = 0; g < 4; g++) {
        float4 v[8];
        #pragma unroll
        for (int j = 0; j < 8; j++)
            v[j] = __ldcs(&e4[(size_t)(g * 8 + j) * (NPIX / 4) + p4]);
        #pragma unroll
        for (int j = 0; j < 8; j++) {
            const int d = g * 8 + j;
            float t;
            t = v[j].x - m0[d]; a0 = fmaf(t, t, a0);
            t = v[j].y - m1[d]; a1 = fmaf(t, t, a1);
            t = v[j].z - m2[d]; a2 = fmaf(t, t, a2);
            t = v[j].w - m3[d]; a3 = fmaf(t, t, a3);
        }
    }

    float h, lacc = 0.0f;
    h = fmaxf(sqrtf(a0) - 0.5f, 0.0f); lacc = fmaf(h * h, wk[kk.x], lacc);
    h = fmaxf(sqrtf(a1) - 0.5f, 0.0f); lacc = fmaf(h * h, wk[kk.y], lacc);
    h = fmaxf(sqrtf(a2) - 0.5f, 0.0f); lacc = fmaf(h * h, wk[kk.z], lacc);
    h = fmaxf(sqrtf(a3) - 0.5f, 0.0f); lacc = fmaf(h * h, wk[kk.w], lacc);

    #pragma unroll
    for (int off = 16; off; off >>= 1)
        lacc += __shfl_down_sync(0xffffffffu, lacc, off);
    if (lane == 0) red[w] = lacc;
    __syncthreads();
    if (tid == 0) {
        float s = 0.0f;
        #pragma unroll
        for (int i = 0; i < P2_TPB / 32; i++) s += red[i];
        atomicAdd(out, s * (1.0f / BB));
    }
}

// ---------------------------------------------------------------------------
extern "C" void kernel_launch(void* const* d_in, const int* in_sizes, int n_in,
                              void* d_out, int out_size) {
    int ei = 0, gi = 1;
    // Defensive: identify inputs by size (embeddings = 67108864, gt = 2097152)
    if (n_in >= 2 && in_sizes[0] == BB * NPIX) { ei = 1; gi = 0; }

    const float* emb = (const float*)d_in[ei];
    const int*   gt  = (const int*)d_in[gi];
    float* out = (float*)d_out;

    k_count<<<dim3(P1_NCHUNK, BB), 256>>>(gt, out);
    k_pass1<<<dim3(P1_NCHUNK, 2, BB), 512>>>(emb, gt);
    k_finalize<<<BB, 256>>>(out);
    k_pass2<<<dim3(P2_BLOCKS, BB), P2_TPB>>>(emb, gt, out);
}

// round 16
// speedup vs baseline: 1.2342x; 1.0576x over previous
#include <cuda_runtime.h>
#include <cstddef>

// Problem constants (fixed by the reference)
#define BB 8
#define DD 32
#define NPIX 262144          // 512*512
#define KK 16

// Pass-1 tiling: 32 pixel-chunks x 2 d-groups x 8 images = 512 blocks
#define P1_CHUNK  8192
#define P1_NCHUNK (NPIX / P1_CHUNK)    // 32

// Pass-2 tiling: one float4 (4 pixels) per thread
#define P2_TPB    256
#define P2_BLOCKS (NPIX / 4 / P2_TPB)  // 256 blocks per image

// Scratch (no cudaMalloc allowed). Partials fully overwritten each launch.
__device__ float g_part[BB * P1_NCHUNK * KK * DD];   // per-chunk partial sums
__device__ float g_cntp[BB * P1_NCHUNK * KK];        // per-chunk partial counts
__device__ float g_counts[BB * KK];
__device__ float g_means[BB * KK * DD];

// ---------------------------------------------------------------------------
// Pass 1: per-image, per-chunk partial segment sums. (R13 structure.)
// Block = 512 threads = 16 warps; warp w owns plane d = dg*16 + w over the
// whole 8192-px chunk. Software-pipelined (distance 1). Embeddings loaded
// with DEFAULT policy (__ldg): first reader, leaves the stream L2-resident
// for pass2.
// COUNT DE-STRAGGLER: label counting no longer rides warp0's main loop
// (which doubled its smem chain and gated half the blocks). In dg0 blocks,
// ALL 512 threads count their 16-label share up-front via spread-address
// smem atomicAdd (~100 cyc once, uniform across warps); the main loop is
// then identical for every warp.
// Per-lane privatized smem bins (stride 32): LDS/FADD/STS conflict-free.
// ---------------------------------------------------------------------------
__global__ __launch_bounds__(512) void k_pass1(const float* __restrict__ emb,
                                               const int* __restrict__ gt,
                                               float* out) {
    __shared__ float acc[16 * KK * 32];          // [w][k][lane]  32 KB
    __shared__ float cnt[KK * 32];               // [k][lane]      2 KB
    __shared__ unsigned int labw[P1_CHUNK / 4];  // packed 4x u8    8 KB

    const int b  = blockIdx.z;
    const int dg = blockIdx.y;                   // d group: 0 or 1
    const int c  = blockIdx.x;                   // chunk
    const int p0 = c * P1_CHUNK;
    const int tid = threadIdx.x;
    const int w   = tid >> 5;
    const int lane = tid & 31;
    const int d = dg * 16 + w;

    if (b == 0 && dg == 0 && c == 0 && tid == 0) out[0] = 0.0f;

    for (int j = tid; j < 16 * KK * 32; j += 512) acc[j] = 0.0f;
    if (tid < KK * 32) cnt[tid] = 0.0f;

    // Stage labels once (int4 -> packed u8x4): 2048 words
    const int4* g4 = (const int4*)(gt + (size_t)b * NPIX + p0);
    for (int j = tid; j < P1_CHUNK / 4; j += 512) {
        int4 t = g4[j];
        labw[j] = (unsigned)t.x | ((unsigned)t.y << 8) |
                  ((unsigned)t.z << 16) | ((unsigned)t.w << 24);
    }
    __syncthreads();

    // Up-front distributed counting (dg0 blocks only): 4 packed words = 16
    // labels per thread, spread-address smem atomics (ATOMS ~2cyc/lane).
    if (dg == 0) {
        #pragma unroll
        for (int j = 0; j < 4; j++) {
            unsigned kw = labw[j * 512 + tid];
            atomicAdd(&cnt[(int)(kw & 15u) * 32 + lane], 1.0f);
            atomicAdd(&cnt[(int)((kw >> 8) & 15u) * 32 + lane], 1.0f);
            atomicAdd(&cnt[(int)((kw >> 16) & 15u) * 32 + lane], 1.0f);
            atomicAdd(&cnt[(int)(kw >> 24) * 32 + lane], 1.0f);
        }
    }

    const float4* e4 = (const float4*)(emb + ((size_t)(b * DD + d)) * NPIX + p0);

    float* aw = acc + (w * KK) * 32 + lane;

    #define RMW(V, KW) do {                                             \
        unsigned kw_ = (KW);                                            \
        aw[(int)(kw_ & 15u) * 32]         += (V).x;                     \
        aw[(int)((kw_ >> 8) & 15u) * 32]  += (V).y;                     \
        aw[(int)((kw_ >> 16) & 15u) * 32] += (V).z;                     \
        aw[(int)(kw_ >> 24) * 32]         += (V).w;                     \
    } while (0)

    // 2048 float4s per plane-chunk per warp; 64 per lane, two per iteration.
    // Software pipeline, prefetch distance 1. Default-policy loads (L2-keep).
    // IDENTICAL work for all 16 warps (no count straggler).
    float4 va = __ldg(&e4[lane]);
    float4 vb = __ldg(&e4[lane + 32]);
    unsigned ka = labw[lane];
    unsigned kb = labw[lane + 32];

    #pragma unroll 1
    for (int i = 0; i < 31; i++) {
        const int nidx = (i + 1) * 64 + lane;
        float4 na = __ldg(&e4[nidx]);
        float4 nb = __ldg(&e4[nidx + 32]);
        unsigned nka = labw[nidx];
        unsigned nkb = labw[nidx + 32];

        RMW(va, ka);
        RMW(vb, kb);

        va = na; vb = nb; ka = nka; kb = nkb;
    }
    RMW(va, ka);
    RMW(vb, kb);
    #undef RMW
    __syncwarp();

    // Epilogue: rows acc[w][k][0..31] are contiguous 128B. 2 lanes per k-row,
    // each reads 4 float4, sum, 1 shuffle, STG (no atomics).
    {
        const int k = lane >> 1;
        const int h = lane & 1;
        const float4* row = (const float4*)(acc + ((w * KK + k) << 5) + (h << 4));
        float4 r0 = row[0], r1 = row[1], r2 = row[2], r3 = row[3];
        float s = ((r0.x + r0.y) + (r0.z + r0.w)) + ((r1.x + r1.y) + (r1.z + r1.w))
                + ((r2.x + r2.y) + (r2.z + r2.w)) + ((r3.x + r3.y) + (r3.z + r3.w));
        s += __shfl_down_sync(0xffffffffu, s, 1);
        if (h == 0)
            g_part[(((b * P1_NCHUNK + c) * KK + k) * DD) + d] = s;
    }

    // Count epilogue: dg is block-uniform, so the conditional sync is legal.
    if (dg == 0) {
        __syncthreads();             // all warps' count atomics visible
        if (w == 0) {
            const int k = lane >> 1;
            const int h = lane & 1;
            const float4* row = (const float4*)(cnt + (k << 5) + (h << 4));
            float4 r0 = row[0], r1 = row[1], r2 = row[2], r3 = row[3];
            float s = ((r0.x + r0.y) + (r0.z + r0.w)) + ((r1.x + r1.y) + (r1.z + r1.w))
                    + ((r2.x + r2.y) + (r2.z + r2.w)) + ((r3.x + r3.y) + (r3.z + r3.w));
            s += __shfl_down_sync(0xffffffffu, s, 1);
            if (h == 0)
                g_cntp[(b * P1_NCHUNK + c) * KK + k] = s;
        }
    }
}

// ---------------------------------------------------------------------------
// Finalize: reduce partials -> counts & means; pairwise push loss; reg loss.
// One block per image.
// ---------------------------------------------------------------------------
__global__ __launch_bounds__(256) void k_finalize(float* out) {
    __shared__ float m[KK * 33];    // padded means
    __shared__ float cs[KK];
    __shared__ float red[256];

    const int b = blockIdx.x;
    const int tid = threadIdx.x;

    if (tid < KK) {
        float s = 0.0f;
        #pragma unroll 4
        for (int c = 0; c < P1_NCHUNK; c++)
            s += g_cntp[(b * P1_NCHUNK + c) * KK + tid];
        float cv = fmaxf(s, 1.0f);
        cs[tid] = cv;
        g_counts[b * KK + tid] = cv;
    }
    __syncthreads();

    for (int j = tid; j < KK * DD; j += 256) {
        int k = j >> 5, d = j & 31;
        float s = 0.0f;
        #pragma unroll 4
        for (int c = 0; c < P1_NCHUNK; c++)
            s += g_part[(((b * P1_NCHUNK + c) * KK + k) * DD) + d];
        float mean = s / cs[k];
        g_means[(b * KK + k) * DD + d] = mean;
        m[k * 33 + d] = mean;
    }
    __syncthreads();

    // Pairwise hinge on cluster-mean distances: thread -> (i,j), upper tri only.
    const int i = tid >> 4;
    const int j = tid & 15;
    float contrib = 0.0f;
    if (j > i) {
        float d2 = 0.0f;
        #pragma unroll
        for (int d = 0; d < DD; d++) {
            float df = m[i * 33 + d] - m[j * 33 + d];
            d2 = fmaf(df, df, d2);
        }
        float pd = sqrtf(d2);             // i<j: diagonal eye irrelevant
        float h = fmaxf(3.0f - pd, 0.0f); // 2 * DIST_THETA = 3.0
        contrib = h * h;
    }

    float reg = 0.0f;
    if (tid < KK) {
        float n2 = 0.0f;
        #pragma unroll
        for (int d = 0; d < DD; d++) {
            float v = m[tid * 33 + d];
            n2 = fmaf(v, v, n2);
        }
        reg = sqrtf(n2);
    }

    red[tid] = contrib * (1.0f / (KK * (KK - 1))) + 0.001f * reg * (1.0f / KK);
    __syncthreads();
    for (int off = 128; off; off >>= 1) {
        if (tid < off) red[tid] += red[tid + off];
        __syncthreads();
    }
    if (tid == 0) atomicAdd(out, red[0] * (1.0f / BB));
}

// ---------------------------------------------------------------------------
// Pass 2: per-pixel hinge variance loss. Reversed traversal (harvest pass1's
// L2 leftovers first); __ldcs = last consumer, evict-first.
// ---------------------------------------------------------------------------
__global__ __launch_bounds__(P2_TPB) void k_pass2(const float* __restrict__ emb,
                                                  const int* __restrict__ gt,
                                                  float* out) {
    __shared__ float m[KK * 33];
    __shared__ float wk[KK];
    __shared__ float red[P2_TPB / 32];

    const int b  = (BB - 1) - blockIdx.y;                 // image reversal
    const int xr = (P2_BLOCKS - 1) - blockIdx.x;          // chunk reversal
    const int tid = threadIdx.x;
    const int lane = tid & 31;
    const int w = tid >> 5;
    const int p4 = xr * P2_TPB + tid;            // float4 index

    for (int j = tid; j < KK * DD; j += P2_TPB)
        m[(j / DD) * 33 + (j % DD)] = g_means[b * KK * DD + j];
    if (tid < KK)
        wk[tid] = 1.0f / ((float)KK * fmaxf(g_counts[b * KK + tid], 1.0f));
    __syncthreads();

    const float4* e4 = (const float4*)(emb + (size_t)b * DD * NPIX);
    const int4 kk = ((const int4*)(gt + (size_t)b * NPIX))[p4];

    const float* m0 = m + kk.x * 33;
    const float* m1 = m + kk.y * 33;
    const float* m2 = m + kk.z * 33;
    const float* m3 = m + kk.w * 33;

    float a0 = 0.0f, a1 = 0.0f, a2 = 0.0f, a3 = 0.0f;
    #pragma unroll
    for (int g = 0; g < 4; g++) {
        float4 v[8];
        #pragma unroll
        for (int j = 0; j < 8; j++)
            v[j] = __ldcs(&e4[(size_t)(g * 8 + j) * (NPIX / 4) + p4]);
        #pragma unroll
        for (int j = 0; j < 8; j++) {
            const int d = g * 8 + j;
            float t;
            t = v[j].x - m0[d]; a0 = fmaf(t, t, a0);
            t = v[j].y - m1[d]; a1 = fmaf(t, t, a1);
            t = v[j].z - m2[d]; a2 = fmaf(t, t, a2);
            t = v[j].w - m3[d]; a3 = fmaf(t, t, a3);
        }
    }

    float h, lacc = 0.0f;
    h = fmaxf(sqrtf(a0) - 0.5f, 0.0f); lacc = fmaf(h * h, wk[kk.x], lacc);
    h = fmaxf(sqrtf(a1) - 0.5f, 0.0f); lacc = fmaf(h * h, wk[kk.y], lacc);
    h = fmaxf(sqrtf(a2) - 0.5f, 0.0f); lacc = fmaf(h * h, wk[kk.z], lacc);
    h = fmaxf(sqrtf(a3) - 0.5f, 0.0f); lacc = fmaf(h * h, wk[kk.w], lacc);

    #pragma unroll
    for (int off = 16; off; off >>= 1)
        lacc += __shfl_down_sync(0xffffffffu, lacc, off);
    if (lane == 0) red[w] = lacc;
    __syncthreads();
    if (tid == 0) {
        float s = 0.0f;
        #pragma unroll
        for (int i = 0; i < P2_TPB / 32; i++) s += red[i];
        atomicAdd(out, s * (1.0f / BB));
    }
}

// ---------------------------------------------------------------------------
extern "C" void kernel_launch(void* const* d_in, const int* in_sizes, int n_in,
                              void* d_out, int out_size) {
    int ei = 0, gi = 1;
    // Defensive: identify inputs by size (embeddings = 67108864, gt = 2097152)
    if (n_in >= 2 && in_sizes[0] == BB * NPIX) { ei = 1; gi = 0; }

    const float* emb = (const float*)d_in[ei];
    const int*   gt  = (const int*)d_in[gi];
    float* out = (float*)d_out;

    k_pass1<<<dim3(P1_NCHUNK, 2, BB), 512>>>(emb, gt, out);
    k_finalize<<<BB, 256>>>(out);
    k_pass2<<<dim3(P2_BLOCKS, BB), P2_TPB>>>(emb, gt, out);
}